// round 11
// baseline (speedup 1.0000x reference)
#include <cuda_runtime.h>
#include <cuda_bf16.h>
#include <math.h>

// Problem constants (T=256, B=256, I=H=512)
#define TT 256
#define BB 256
#define KK 512          // u32 words per split row (hi/lo pair words)
#define HH 512
#define G3 1536
#define LN_EPS 1e-5f

// Scratch (static device globals — allocation-free)
__device__ float    g_gi[(size_t)TT * BB * G3];  // (T*B, 3H) input projections
__device__ float    g_gh[(size_t)BB * G3];       // (B, 3H) per-step hidden proj
__device__ float    g_h [(size_t)BB * HH];       // (B, H) fp32 hidden state
__device__ unsigned g_xs [(size_t)TT * BB * KK]; // x split (bf16 hi/lo words)
__device__ unsigned g_wis[(size_t)G3 * KK];      // W_ih split
__device__ unsigned g_whs[(size_t)G3 * KK];      // W_hh split
__device__ unsigned g_hs [(size_t)BB * KK];      // h split (updated each step)
__device__ unsigned g_cnt[TT * 8];               // per-(step, m-group) arrival counters

// PDL primitives (no-ops when launched without the PDL attribute)
__device__ __forceinline__ void pdl_wait()    { asm volatile("griddepcontrol.wait;" ::: "memory"); }
__device__ __forceinline__ void pdl_trigger() { asm volatile("griddepcontrol.launch_dependents;" ::: "memory"); }

// ---------------------------------------------------------------------------
// bf16 split helpers. word(2p)=hi bf16x2 of elem pair p, word(2p+1)=lo.
// ---------------------------------------------------------------------------
__device__ __forceinline__ uint2 split2(float x, float y) {
    __nv_bfloat16 hx = __float2bfloat16(x);
    __nv_bfloat16 hy = __float2bfloat16(y);
    __nv_bfloat16 lx = __float2bfloat16(x - __bfloat162float(hx));
    __nv_bfloat16 ly = __float2bfloat16(y - __bfloat162float(hy));
    __nv_bfloat162 hp; hp.x = hx; hp.y = hy;
    __nv_bfloat162 lp; lp.x = lx; lp.y = ly;
    uint2 o;
    o.x = *reinterpret_cast<unsigned*>(&hp);
    o.y = *reinterpret_cast<unsigned*>(&lp);
    return o;
}

__global__ void split_pairs(const float* __restrict__ src,
                            unsigned* __restrict__ dst, int npairs) {
    int i = blockIdx.x * 256 + threadIdx.x;
    if (i >= npairs) return;
    float2 v = ((const float2*)src)[i];
    ((uint2*)dst)[i] = split2(v.x, v.y);
}

__global__ void zero_cnt() {
    g_cnt[blockIdx.x * 256 + threadIdx.x] = 0u;
}

__device__ __forceinline__ void mma_bf16(float* d, unsigned a0, unsigned a1,
                                         unsigned a2, unsigned a3,
                                         unsigned b0, unsigned b1) {
    asm volatile(
        "mma.sync.aligned.m16n8k16.row.col.f32.bf16.bf16.f32 "
        "{%0,%1,%2,%3},{%4,%5,%6,%7},{%8,%9},{%0,%1,%2,%3};"
        : "+f"(d[0]), "+f"(d[1]), "+f"(d[2]), "+f"(d[3])
        : "r"(a0), "r"(a1), "r"(a2), "r"(a3), "r"(b0), "r"(b1));
}

// ---------------------------------------------------------------------------
// gi GEMM (phase 1, fully parallel): 64x64 tile, proven since R6.
// ---------------------------------------------------------------------------
__global__ __launch_bounds__(256, 2) void gemm_bf16s(
    const unsigned* __restrict__ A, const unsigned* __restrict__ W,
    const float* __restrict__ bias, float* __restrict__ C, int ldc)
{
    __shared__ unsigned sA[2][64 * 24];
    __shared__ unsigned sW[2][64 * 24];

    const int tid  = threadIdx.x;
    const int wid  = tid >> 5;
    const int lane = tid & 31;
    const int qr   = lane >> 2;
    const int qc   = lane & 3;
    const int m0   = blockIdx.y * 64;
    const int n0   = blockIdx.x * 64;
    const int m_off = (wid >> 2) * 32;
    const int n_off = (wid & 3) * 16;

    const int srow = tid >> 2;
    const int sq   = tid & 3;
    const int ws0  = 2 * ((2 * sq) & 3) + ((2 * sq) >> 2);
    const int ws1  = 2 * ((2 * sq + 1) & 3) + ((2 * sq + 1) >> 2);
    const unsigned* Wp = W + (size_t)(n0 + srow) * KK + sq * 4;
    const unsigned* Ap = A + (size_t)(m0 + srow) * KK + sq * 4;

    float acc[2][2][4];
    #pragma unroll
    for (int mt = 0; mt < 2; mt++)
        #pragma unroll
        for (int nt = 0; nt < 2; nt++)
            #pragma unroll
            for (int c = 0; c < 4; c++) acc[mt][nt][c] = 0.0f;

    {
        uint4 wv = *(const uint4*)Wp;
        uint4 av = *(const uint4*)Ap;
        sW[0][srow * 24 + ws0]     = wv.x;
        sW[0][srow * 24 + 8 + ws0] = wv.y;
        sW[0][srow * 24 + ws1]     = wv.z;
        sW[0][srow * 24 + 8 + ws1] = wv.w;
        sA[0][srow * 24 + ws0]     = av.x;
        sA[0][srow * 24 + 8 + ws0] = av.y;
        sA[0][srow * 24 + ws1]     = av.z;
        sA[0][srow * 24 + 8 + ws1] = av.w;
    }
    __syncthreads();

    uint4 wnx, anx;
    for (int ch = 0; ch < 32; ++ch) {
        const int cur = ch & 1;
        if (ch < 31) {
            wnx = *(const uint4*)(Wp + (ch + 1) * 16);
            anx = *(const uint4*)(Ap + (ch + 1) * 16);
        }

        const unsigned* pA = sA[cur];
        const unsigned* pW = sW[cur];
        unsigned ah[2][4], al[2][4];
        #pragma unroll
        for (int mt = 0; mt < 2; mt++) {
            const int r = m_off + mt * 16 + qr;
            uint2 h0 = *(const uint2*)(pA + r * 24 + 2 * qc);
            uint2 h1 = *(const uint2*)(pA + (r + 8) * 24 + 2 * qc);
            uint2 l0 = *(const uint2*)(pA + r * 24 + 8 + 2 * qc);
            uint2 l1 = *(const uint2*)(pA + (r + 8) * 24 + 8 + 2 * qc);
            ah[mt][0] = h0.x; ah[mt][1] = h1.x; ah[mt][2] = h0.y; ah[mt][3] = h1.y;
            al[mt][0] = l0.x; al[mt][1] = l1.x; al[mt][2] = l0.y; al[mt][3] = l1.y;
        }
        #pragma unroll
        for (int nt = 0; nt < 2; nt++) {
            const int rn = n_off + nt * 8 + qr;
            uint2 bh = *(const uint2*)(pW + rn * 24 + 2 * qc);
            uint2 bl = *(const uint2*)(pW + rn * 24 + 8 + 2 * qc);
            #pragma unroll
            for (int mt = 0; mt < 2; mt++) {
                mma_bf16(acc[mt][nt], ah[mt][0], ah[mt][1], ah[mt][2], ah[mt][3], bh.x, bh.y);
                mma_bf16(acc[mt][nt], ah[mt][0], ah[mt][1], ah[mt][2], ah[mt][3], bl.x, bl.y);
                mma_bf16(acc[mt][nt], al[mt][0], al[mt][1], al[mt][2], al[mt][3], bh.x, bh.y);
            }
        }

        if (ch < 31) {
            const int nb = cur ^ 1;
            sW[nb][srow * 24 + ws0]     = wnx.x;
            sW[nb][srow * 24 + 8 + ws0] = wnx.y;
            sW[nb][srow * 24 + ws1]     = wnx.z;
            sW[nb][srow * 24 + 8 + ws1] = wnx.w;
            sA[nb][srow * 24 + ws0]     = anx.x;
            sA[nb][srow * 24 + 8 + ws0] = anx.y;
            sA[nb][srow * 24 + ws1]     = anx.z;
            sA[nb][srow * 24 + 8 + ws1] = anx.w;
        }
        __syncthreads();
    }

    #pragma unroll
    for (int mt = 0; mt < 2; mt++)
        #pragma unroll
        for (int nt = 0; nt < 2; nt++) {
            const int r = m0 + m_off + mt * 16 + qr;
            const int c = n0 + n_off + nt * 8 + qc * 2;
            const float bx = bias[c], by = bias[c + 1];
            *(float2*)(C + (size_t)r * ldc + c) =
                make_float2(acc[mt][nt][0] + bx, acc[mt][nt][1] + by);
            *(float2*)(C + (size_t)(r + 8) * ldc + c) =
                make_float2(acc[mt][nt][2] + bx, acc[mt][nt][3] + by);
        }
}

// ---------------------------------------------------------------------------
// Fused step kernel: GEMM (32x64 tile) + tail-finisher gate/LN.
// Grid (24 n, 8 m) = 192 blocks. Per m-group, the last 8 arriving blocks
// each handle 4 rows of gates+LN+h-update. One launch per step, PDL-chained.
// ---------------------------------------------------------------------------
__global__ __launch_bounds__(256, 2) void step_kernel(
    int t, const float* __restrict__ masks, const float* __restrict__ b_hh,
    const float* __restrict__ ln_w, const float* __restrict__ ln_b,
    float* __restrict__ y)
{
    __shared__ unsigned sA[2][32 * 24];
    __shared__ unsigned sW[2][64 * 24];
    __shared__ unsigned s_old;
    __shared__ float rs1[4][2], rs2[4][2];

    const int tid  = threadIdx.x;
    const int wid  = tid >> 5;
    const int lane = tid & 31;
    const int qr   = lane >> 2;
    const int qc   = lane & 3;
    const int mg   = blockIdx.y;           // 0..7
    const int m0   = mg * 32;
    const int n0   = blockIdx.x * 64;
    const int m_off = (wid >> 2) * 16;
    const int n_off = (wid & 3) * 16;

    // W staging: 4 threads/row, 4 words each
    const int wrow = tid >> 2;
    const int sq   = tid & 3;
    const int ws0  = 2 * ((2 * sq) & 3) + ((2 * sq) >> 2);
    const int ws1  = 2 * ((2 * sq + 1) & 3) + ((2 * sq + 1) >> 2);
    const unsigned* Wp = g_whs + (size_t)(n0 + wrow) * KK + sq * 4;

    // A staging: 8 threads/row, 2 words (pair j)
    const int arow = tid >> 3;
    const int aj   = tid & 7;
    const int as0  = 2 * (aj & 3) + (aj >> 2);
    const unsigned* Ap = g_hs + (size_t)(m0 + arow) * KK + aj * 2;

    float acc[2][4];
    #pragma unroll
    for (int nt = 0; nt < 2; nt++)
        #pragma unroll
        for (int c = 0; c < 4; c++) acc[nt][c] = 0.0f;

    // chunk 0: W pre-wait (constant), A post-wait (depends on prev step)
    {
        uint4 wv = *(const uint4*)Wp;
        sW[0][wrow * 24 + ws0]     = wv.x;
        sW[0][wrow * 24 + 8 + ws0] = wv.y;
        sW[0][wrow * 24 + ws1]     = wv.z;
        sW[0][wrow * 24 + 8 + ws1] = wv.w;
        pdl_wait();
        const unsigned mzs =
            (__ldg(masks + t * BB + m0 + arow) != 0.0f) ? 0xFFFFFFFFu : 0u;
        uint2 av = __ldcg((const uint2*)Ap);
        sA[0][arow * 24 + as0]     = av.x & mzs;
        sA[0][arow * 24 + 8 + as0] = av.y & mzs;
    }
    const unsigned mz =
        (__ldg(masks + t * BB + m0 + arow) != 0.0f) ? 0xFFFFFFFFu : 0u;
    __syncthreads();

    uint4 wnx; uint2 anx;
    for (int ch = 0; ch < 32; ++ch) {
        const int cur = ch & 1;
        if (ch < 31) {
            wnx = *(const uint4*)(Wp + (ch + 1) * 16);
            anx = __ldcg((const uint2*)(Ap + (ch + 1) * 16));
        }

        const unsigned* pA = sA[cur];
        const unsigned* pW = sW[cur];
        const int r = m_off + qr;
        uint2 h0 = *(const uint2*)(pA + r * 24 + 2 * qc);
        uint2 h1 = *(const uint2*)(pA + (r + 8) * 24 + 2 * qc);
        uint2 l0 = *(const uint2*)(pA + r * 24 + 8 + 2 * qc);
        uint2 l1 = *(const uint2*)(pA + (r + 8) * 24 + 8 + 2 * qc);
        #pragma unroll
        for (int nt = 0; nt < 2; nt++) {
            const int rn = n_off + nt * 8 + qr;
            uint2 bh = *(const uint2*)(pW + rn * 24 + 2 * qc);
            uint2 bl = *(const uint2*)(pW + rn * 24 + 8 + 2 * qc);
            mma_bf16(acc[nt], h0.x, h1.x, h0.y, h1.y, bh.x, bh.y);
            mma_bf16(acc[nt], h0.x, h1.x, h0.y, h1.y, bl.x, bl.y);
            mma_bf16(acc[nt], l0.x, l1.x, l0.y, l1.y, bh.x, bh.y);
        }

        if (ch < 31) {
            const int nb = cur ^ 1;
            sW[nb][wrow * 24 + ws0]     = wnx.x;
            sW[nb][wrow * 24 + 8 + ws0] = wnx.y;
            sW[nb][wrow * 24 + ws1]     = wnx.z;
            sW[nb][wrow * 24 + 8 + ws1] = wnx.w;
            sA[nb][arow * 24 + as0]     = anx.x & mz;
            sA[nb][arow * 24 + 8 + as0] = anx.y & mz;
        }
        __syncthreads();
    }

    // write gh tile (+ b_hh)
    #pragma unroll
    for (int nt = 0; nt < 2; nt++) {
        const int r = m0 + m_off + qr;
        const int c = n0 + n_off + nt * 8 + qc * 2;
        const float bx = b_hh[c], by = b_hh[c + 1];
        *(float2*)(g_gh + (size_t)r * G3 + c) =
            make_float2(acc[nt][0] + bx, acc[nt][1] + by);
        *(float2*)(g_gh + (size_t)(r + 8) * G3 + c) =
            make_float2(acc[nt][2] + bx, acc[nt][3] + by);
    }

    // ---- arrival accounting ----
    __syncthreads();
    if (tid == 0) {
        __threadfence();                       // publish gh tile
        s_old = atomicAdd(&g_cnt[t * 8 + mg], 1u);
    }
    __syncthreads();
    const unsigned old = s_old;

    if (old >= 16u) {
        // ---- finisher: 4 rows of gate + LN + h update ----
        if (tid == 0) {
            volatile unsigned* c = &g_cnt[t * 8 + mg];
            while (*c < 24u) { __nanosleep(32); }
        }
        __syncthreads();
        __threadfence();                       // acquire all 24 gh tiles

        const int idx  = (int)old - 16;        // 0..7
        const int rl   = tid >> 6;             // row-in-quad 0..3
        const int l64  = tid & 63;
        const int row  = m0 + idx * 4 + rl;
        const int w2   = (tid >> 5) & 1;

        const float m = __ldg(masks + t * BB + row);
        const float* gi = g_gi + ((size_t)t * BB + row) * G3;
        const float* gh = g_gh + (size_t)row * G3;
        float* hp = g_h + (size_t)row * HH;

        float2 hv[4];
        float s1 = 0.f, s2 = 0.f;
        #pragma unroll
        for (int i = 0; i < 4; i++) {
            const int j = 2 * l64 + 128 * i;
            float2 gir = *(const float2*)(gi + j);
            float2 giz = *(const float2*)(gi + HH + j);
            float2 gin = *(const float2*)(gi + 2 * HH + j);
            float2 ghr = __ldcg((const float2*)(gh + j));
            float2 ghz = __ldcg((const float2*)(gh + HH + j));
            float2 ghn = __ldcg((const float2*)(gh + 2 * HH + j));
            float2 hpp = *(const float2*)(hp + j);
            const float r0 = 1.f / (1.f + expf(-(gir.x + ghr.x)));
            const float r1 = 1.f / (1.f + expf(-(gir.y + ghr.y)));
            const float z0 = 1.f / (1.f + expf(-(giz.x + ghz.x)));
            const float z1 = 1.f / (1.f + expf(-(giz.y + ghz.y)));
            const float n0f = tanhf(gin.x + r0 * ghn.x);
            const float n1f = tanhf(gin.y + r1 * ghn.y);
            const float h0 = (1.f - z0) * n0f + z0 * (hpp.x * m);
            const float h1 = (1.f - z1) * n1f + z1 * (hpp.y * m);
            hv[i] = make_float2(h0, h1);
            s1 += h0 + h1; s2 += h0 * h0 + h1 * h1;
        }
        // reduce over the 64 threads of this row (2 warps)
        #pragma unroll
        for (int o = 16; o > 0; o >>= 1) {
            s1 += __shfl_xor_sync(0xFFFFFFFFu, s1, o);
            s2 += __shfl_xor_sync(0xFFFFFFFFu, s2, o);
        }
        if (lane == 0) { rs1[rl][w2] = s1; rs2[rl][w2] = s2; }
        __syncthreads();
        const float S1 = rs1[rl][0] + rs1[rl][1];
        const float S2 = rs2[rl][0] + rs2[rl][1];
        const float mu   = S1 * (1.f / HH);
        const float rstd = rsqrtf(S2 * (1.f / HH) - mu * mu + LN_EPS);

        float* yp = y + ((size_t)t * BB + row) * HH;
        uint2* hsp = (uint2*)(g_hs + (size_t)row * KK);
        #pragma unroll
        for (int i = 0; i < 4; i++) {
            const int j = 2 * l64 + 128 * i;
            const float h0 = hv[i].x, h1 = hv[i].y;
            *(float2*)(hp + j) = make_float2(h0, h1);
            hsp[j >> 1] = split2(h0, h1);
            float2 w  = *(const float2*)(ln_w + j);
            float2 bb = *(const float2*)(ln_b + j);
            *(float2*)(yp + j) = make_float2((h0 - mu) * rstd * w.x + bb.x,
                                             (h1 - mu) * rstd * w.y + bb.y);
        }
    }
    pdl_trigger();
}

// ---------------------------------------------------------------------------
// PDL launch helper
// ---------------------------------------------------------------------------
template<typename F, typename... Args>
static inline void launch_pdl(F f, dim3 grid, dim3 block, Args... args) {
    cudaLaunchConfig_t cfg = {};
    cfg.gridDim = grid;
    cfg.blockDim = block;
    cfg.dynamicSmemBytes = 0;
    cfg.stream = 0;
    cudaLaunchAttribute attr[1];
    attr[0].id = cudaLaunchAttributeProgrammaticStreamSerialization;
    attr[0].val.programmaticStreamSerializationAllowed = 1;
    cfg.attrs = attr;
    cfg.numAttrs = 1;
    cudaLaunchKernelEx(&cfg, f, args...);
}

// ---------------------------------------------------------------------------
extern "C" void kernel_launch(void* const* d_in, const int* in_sizes, int n_in,
                              void* d_out, int out_size)
{
    const float* x     = (const float*)d_in[0];
    const float* h0    = (const float*)d_in[1];
    const float* masks = (const float*)d_in[2];
    const float* W_ih  = (const float*)d_in[3];
    const float* W_hh  = (const float*)d_in[4];
    const float* b_ih  = (const float*)d_in[5];
    const float* b_hh  = (const float*)d_in[6];
    const float* ln_w  = (const float*)d_in[7];
    const float* ln_b  = (const float*)d_in[8];

    float* y  = (float*)d_out;
    float* hT = y + (size_t)TT * BB * HH;

    float *gi_p, *h_p;
    unsigned *xs_p, *wis_p, *whs_p, *hs_p;
    cudaGetSymbolAddress((void**)&gi_p,  g_gi);
    cudaGetSymbolAddress((void**)&h_p,   g_h);
    cudaGetSymbolAddress((void**)&xs_p,  g_xs);
    cudaGetSymbolAddress((void**)&wis_p, g_wis);
    cudaGetSymbolAddress((void**)&whs_p, g_whs);
    cudaGetSymbolAddress((void**)&hs_p,  g_hs);

    // Phase 0: counters + one-time bf16 hi/lo splits
    zero_cnt<<<TT * 8 / 256, 256>>>();
    const int npx = TT * BB * KK / 2;
    const int npw = G3 * KK / 2;
    const int nph = BB * HH / 2;
    split_pairs<<<(npx + 255) / 256, 256>>>(x,    xs_p,  npx);
    split_pairs<<<(npw + 255) / 256, 256>>>(W_ih, wis_p, npw);
    split_pairs<<<(npw + 255) / 256, 256>>>(W_hh, whs_p, npw);
    split_pairs<<<(nph + 255) / 256, 256>>>(h0,   hs_p,  nph);
    cudaMemcpyAsync(h_p, h0, (size_t)BB * HH * sizeof(float),
                    cudaMemcpyDeviceToDevice);

    // Phase 1: gi = x @ W_ih^T + b_ih (fully parallel)
    gemm_bf16s<<<dim3(G3 / 64, (TT * BB) / 64), 256>>>(xs_p, wis_p, b_ih, gi_p, G3);

    // Phase 2: ONE fused kernel per step, PDL-chained
    for (int t = 0; t < TT; t++) {
        launch_pdl(step_kernel, dim3(G3 / 64, BB / 32), dim3(256),
                   t, masks, b_hh, ln_w, ln_b, y);
    }

    // hT output
    cudaMemcpyAsync(hT, h_p, (size_t)BB * HH * sizeof(float),
                    cudaMemcpyDeviceToDevice);
}

// round 12
// speedup vs baseline: 1.3084x; 1.3084x over previous
#include <cuda_runtime.h>
#include <cuda_bf16.h>
#include <math.h>

// Problem constants (T=256, B=256, I=H=512)
#define TT 256
#define BB 256
#define KK 512          // u32 words per split row (hi/lo pair words)
#define HH 512
#define G3 1536
#define LN_EPS 1e-5f

// Scratch (static device globals — allocation-free)
__device__ float    g_gi[(size_t)TT * BB * G3];  // (T*B, 3H) input projections
__device__ float    g_gh[(size_t)BB * G3];       // (B, 3H) per-step hidden proj
__device__ float    g_h [(size_t)BB * HH];       // (B, H) fp32 hidden state
__device__ unsigned g_xs [(size_t)TT * BB * KK]; // x split (bf16 hi/lo words)
__device__ unsigned g_wis[(size_t)G3 * KK];      // W_ih split
__device__ unsigned g_whs[(size_t)G3 * KK];      // W_hh split
__device__ unsigned g_hs [(size_t)BB * KK];      // h split (updated each step)

// PDL primitives (no-ops when launched without the PDL attribute)
__device__ __forceinline__ void pdl_wait()    { asm volatile("griddepcontrol.wait;" ::: "memory"); }
__device__ __forceinline__ void pdl_trigger() { asm volatile("griddepcontrol.launch_dependents;" ::: "memory"); }

// ---------------------------------------------------------------------------
// bf16 split helpers. word(2p)=hi bf16x2 of elem pair p, word(2p+1)=lo.
// ---------------------------------------------------------------------------
__device__ __forceinline__ uint2 split2(float x, float y) {
    __nv_bfloat16 hx = __float2bfloat16(x);
    __nv_bfloat16 hy = __float2bfloat16(y);
    __nv_bfloat16 lx = __float2bfloat16(x - __bfloat162float(hx));
    __nv_bfloat16 ly = __float2bfloat16(y - __bfloat162float(hy));
    __nv_bfloat162 hp; hp.x = hx; hp.y = hy;
    __nv_bfloat162 lp; lp.x = lx; lp.y = ly;
    uint2 o;
    o.x = *reinterpret_cast<unsigned*>(&hp);
    o.y = *reinterpret_cast<unsigned*>(&lp);
    return o;
}

__global__ void split_pairs(const float* __restrict__ src,
                            unsigned* __restrict__ dst, int npairs) {
    int i = blockIdx.x * 256 + threadIdx.x;
    if (i >= npairs) return;
    float2 v = ((const float2*)src)[i];
    ((uint2*)dst)[i] = split2(v.x, v.y);
}

__device__ __forceinline__ void mma_bf16(float* d, unsigned a0, unsigned a1,
                                         unsigned a2, unsigned a3,
                                         unsigned b0, unsigned b1) {
    asm volatile(
        "mma.sync.aligned.m16n8k16.row.col.f32.bf16.bf16.f32 "
        "{%0,%1,%2,%3},{%4,%5,%6,%7},{%8,%9},{%0,%1,%2,%3};"
        : "+f"(d[0]), "+f"(d[1]), "+f"(d[2]), "+f"(d[3])
        : "r"(a0), "r"(a1), "r"(a2), "r"(a3), "r"(b0), "r"(b1));
}

// ---------------------------------------------------------------------------
// gi GEMM (phase 1, fully parallel): 64x64 tile, k-chunk 16 — proven since R6.
// ---------------------------------------------------------------------------
__global__ __launch_bounds__(256, 2) void gemm_bf16s(
    const unsigned* __restrict__ A, const unsigned* __restrict__ W,
    const float* __restrict__ bias, float* __restrict__ C, int ldc)
{
    __shared__ unsigned sA[2][64 * 24];
    __shared__ unsigned sW[2][64 * 24];

    const int tid  = threadIdx.x;
    const int wid  = tid >> 5;
    const int lane = tid & 31;
    const int qr   = lane >> 2;
    const int qc   = lane & 3;
    const int m0   = blockIdx.y * 64;
    const int n0   = blockIdx.x * 64;
    const int m_off = (wid >> 2) * 32;
    const int n_off = (wid & 3) * 16;

    const int srow = tid >> 2;
    const int sq   = tid & 3;
    const int ws0  = 2 * ((2 * sq) & 3) + ((2 * sq) >> 2);
    const int ws1  = 2 * ((2 * sq + 1) & 3) + ((2 * sq + 1) >> 2);
    const unsigned* Wp = W + (size_t)(n0 + srow) * KK + sq * 4;
    const unsigned* Ap = A + (size_t)(m0 + srow) * KK + sq * 4;

    float acc[2][2][4];
    #pragma unroll
    for (int mt = 0; mt < 2; mt++)
        #pragma unroll
        for (int nt = 0; nt < 2; nt++)
            #pragma unroll
            for (int c = 0; c < 4; c++) acc[mt][nt][c] = 0.0f;

    {
        uint4 wv = *(const uint4*)Wp;
        uint4 av = *(const uint4*)Ap;
        sW[0][srow * 24 + ws0]     = wv.x;
        sW[0][srow * 24 + 8 + ws0] = wv.y;
        sW[0][srow * 24 + ws1]     = wv.z;
        sW[0][srow * 24 + 8 + ws1] = wv.w;
        sA[0][srow * 24 + ws0]     = av.x;
        sA[0][srow * 24 + 8 + ws0] = av.y;
        sA[0][srow * 24 + ws1]     = av.z;
        sA[0][srow * 24 + 8 + ws1] = av.w;
    }
    __syncthreads();

    uint4 wnx, anx;
    for (int ch = 0; ch < 32; ++ch) {
        const int cur = ch & 1;
        if (ch < 31) {
            wnx = *(const uint4*)(Wp + (ch + 1) * 16);
            anx = *(const uint4*)(Ap + (ch + 1) * 16);
        }

        const unsigned* pA = sA[cur];
        const unsigned* pW = sW[cur];
        unsigned ah[2][4], al[2][4];
        #pragma unroll
        for (int mt = 0; mt < 2; mt++) {
            const int r = m_off + mt * 16 + qr;
            uint2 h0 = *(const uint2*)(pA + r * 24 + 2 * qc);
            uint2 h1 = *(const uint2*)(pA + (r + 8) * 24 + 2 * qc);
            uint2 l0 = *(const uint2*)(pA + r * 24 + 8 + 2 * qc);
            uint2 l1 = *(const uint2*)(pA + (r + 8) * 24 + 8 + 2 * qc);
            ah[mt][0] = h0.x; ah[mt][1] = h1.x; ah[mt][2] = h0.y; ah[mt][3] = h1.y;
            al[mt][0] = l0.x; al[mt][1] = l1.x; al[mt][2] = l0.y; al[mt][3] = l1.y;
        }
        #pragma unroll
        for (int nt = 0; nt < 2; nt++) {
            const int rn = n_off + nt * 8 + qr;
            uint2 bh = *(const uint2*)(pW + rn * 24 + 2 * qc);
            uint2 bl = *(const uint2*)(pW + rn * 24 + 8 + 2 * qc);
            #pragma unroll
            for (int mt = 0; mt < 2; mt++) {
                mma_bf16(acc[mt][nt], ah[mt][0], ah[mt][1], ah[mt][2], ah[mt][3], bh.x, bh.y);
                mma_bf16(acc[mt][nt], ah[mt][0], ah[mt][1], ah[mt][2], ah[mt][3], bl.x, bl.y);
                mma_bf16(acc[mt][nt], al[mt][0], al[mt][1], al[mt][2], al[mt][3], bh.x, bh.y);
            }
        }

        if (ch < 31) {
            const int nb = cur ^ 1;
            sW[nb][srow * 24 + ws0]     = wnx.x;
            sW[nb][srow * 24 + 8 + ws0] = wnx.y;
            sW[nb][srow * 24 + ws1]     = wnx.z;
            sW[nb][srow * 24 + 8 + ws1] = wnx.w;
            sA[nb][srow * 24 + ws0]     = anx.x;
            sA[nb][srow * 24 + 8 + ws0] = anx.y;
            sA[nb][srow * 24 + ws1]     = anx.z;
            sA[nb][srow * 24 + 8 + ws1] = anx.w;
        }
        __syncthreads();
    }

    #pragma unroll
    for (int mt = 0; mt < 2; mt++)
        #pragma unroll
        for (int nt = 0; nt < 2; nt++) {
            const int r = m0 + m_off + mt * 16 + qr;
            const int c = n0 + n_off + nt * 8 + qc * 2;
            const float bx = bias[c], by = bias[c + 1];
            *(float2*)(C + (size_t)r * ldc + c) =
                make_float2(acc[mt][nt][0] + bx, acc[mt][nt][1] + by);
            *(float2*)(C + (size_t)(r + 8) * ldc + c) =
                make_float2(acc[mt][nt][2] + bx, acc[mt][nt][3] + by);
        }
}

// ---------------------------------------------------------------------------
// Recurrence GEMM: gh = (h*mask) @ W_hh^T + b_hh.
// 64x64 tile, grid (24, 4) = 96 blocks (single wave on 148 SMs).
// k-chunk 32 = two 16-k sub-chunks per buffer: 24 MMAs/warp between syncs,
// register prefetch distance ~= L2 latency; 16 syncs total.
// PDL: W chunk-0 staged pre-wait (constant), A (g_hs) touched post-wait.
// ---------------------------------------------------------------------------
__global__ __launch_bounds__(256, 2) void gemm_rec(
    const float* __restrict__ rowScale, const float* __restrict__ bias)
{
    __shared__ unsigned sA[2][2 * 64 * 24];   // [buf][sub*1536 + row*24 + slot]
    __shared__ unsigned sW[2][2 * 64 * 24];

    const int tid  = threadIdx.x;
    const int wid  = tid >> 5;
    const int lane = tid & 31;
    const int qr   = lane >> 2;
    const int qc   = lane & 3;
    const int m0   = blockIdx.y * 64;
    const int n0   = blockIdx.x * 64;
    const int m_off = (wid >> 2) * 32;
    const int n_off = (wid & 3) * 16;

    const int srow = tid >> 2;
    const int sq   = tid & 3;
    const int ws0  = 2 * ((2 * sq) & 3) + ((2 * sq) >> 2);
    const int ws1  = 2 * ((2 * sq + 1) & 3) + ((2 * sq + 1) >> 2);
    const unsigned* Wp = g_whs + (size_t)(n0 + srow) * KK + sq * 4;
    const unsigned* Ap = g_hs  + (size_t)(m0 + srow) * KK + sq * 4;

    float acc[2][2][4];
    #pragma unroll
    for (int mt = 0; mt < 2; mt++)
        #pragma unroll
        for (int nt = 0; nt < 2; nt++)
            #pragma unroll
            for (int c = 0; c < 4; c++) acc[mt][nt][c] = 0.0f;

    // mask is a harness input (constant for the step) — safe pre-wait
    const unsigned mz = (rowScale[m0 + srow] != 0.0f) ? 0xFFFFFFFFu : 0u;

    // chunk-0 staging: W pre-wait, A post-wait
    {
        #pragma unroll
        for (int s = 0; s < 2; s++) {
            uint4 wv = *(const uint4*)(Wp + s * 16);
            unsigned* d = &sW[0][s * 1536 + srow * 24];
            d[ws0] = wv.x; d[8 + ws0] = wv.y;
            d[ws1] = wv.z; d[8 + ws1] = wv.w;
        }
        pdl_wait();
        #pragma unroll
        for (int s = 0; s < 2; s++) {
            uint4 av = __ldcg((const uint4*)(Ap + s * 16));
            unsigned* d = &sA[0][s * 1536 + srow * 24];
            d[ws0] = av.x & mz; d[8 + ws0] = av.y & mz;
            d[ws1] = av.z & mz; d[8 + ws1] = av.w & mz;
        }
    }
    __syncthreads();

    uint4 wnx[2], anx[2];
    for (int ch = 0; ch < 16; ++ch) {
        const int cur = ch & 1;
        if (ch < 15) {
            #pragma unroll
            for (int s = 0; s < 2; s++) {
                wnx[s] = *(const uint4*)(Wp + (ch + 1) * 32 + s * 16);
                anx[s] = __ldcg((const uint4*)(Ap + (ch + 1) * 32 + s * 16));
            }
        }

        #pragma unroll
        for (int s = 0; s < 2; s++) {
            const unsigned* pA = &sA[cur][s * 1536];
            const unsigned* pW = &sW[cur][s * 1536];
            unsigned ah[2][4], al[2][4];
            #pragma unroll
            for (int mt = 0; mt < 2; mt++) {
                const int r = m_off + mt * 16 + qr;
                uint2 h0 = *(const uint2*)(pA + r * 24 + 2 * qc);
                uint2 h1 = *(const uint2*)(pA + (r + 8) * 24 + 2 * qc);
                uint2 l0 = *(const uint2*)(pA + r * 24 + 8 + 2 * qc);
                uint2 l1 = *(const uint2*)(pA + (r + 8) * 24 + 8 + 2 * qc);
                ah[mt][0] = h0.x; ah[mt][1] = h1.x; ah[mt][2] = h0.y; ah[mt][3] = h1.y;
                al[mt][0] = l0.x; al[mt][1] = l1.x; al[mt][2] = l0.y; al[mt][3] = l1.y;
            }
            #pragma unroll
            for (int nt = 0; nt < 2; nt++) {
                const int rn = n_off + nt * 8 + qr;
                uint2 bh = *(const uint2*)(pW + rn * 24 + 2 * qc);
                uint2 bl = *(const uint2*)(pW + rn * 24 + 8 + 2 * qc);
                #pragma unroll
                for (int mt = 0; mt < 2; mt++) {
                    mma_bf16(acc[mt][nt], ah[mt][0], ah[mt][1], ah[mt][2], ah[mt][3], bh.x, bh.y);
                    mma_bf16(acc[mt][nt], ah[mt][0], ah[mt][1], ah[mt][2], ah[mt][3], bl.x, bl.y);
                    mma_bf16(acc[mt][nt], al[mt][0], al[mt][1], al[mt][2], al[mt][3], bh.x, bh.y);
                }
            }
        }

        if (ch < 15) {
            const int nb = cur ^ 1;
            #pragma unroll
            for (int s = 0; s < 2; s++) {
                unsigned* dW = &sW[nb][s * 1536 + srow * 24];
                dW[ws0] = wnx[s].x; dW[8 + ws0] = wnx[s].y;
                dW[ws1] = wnx[s].z; dW[8 + ws1] = wnx[s].w;
                unsigned* dA = &sA[nb][s * 1536 + srow * 24];
                dA[ws0] = anx[s].x & mz; dA[8 + ws0] = anx[s].y & mz;
                dA[ws1] = anx[s].z & mz; dA[8 + ws1] = anx[s].w & mz;
            }
        }
        __syncthreads();
    }

    #pragma unroll
    for (int mt = 0; mt < 2; mt++)
        #pragma unroll
        for (int nt = 0; nt < 2; nt++) {
            const int r = m0 + m_off + mt * 16 + qr;
            const int c = n0 + n_off + nt * 8 + qc * 2;
            const float bx = bias[c], by = bias[c + 1];
            *(float2*)(g_gh + (size_t)r * G3 + c) =
                make_float2(acc[mt][nt][0] + bx, acc[mt][nt][1] + by);
            *(float2*)(g_gh + (size_t)(r + 8) * G3 + c) =
                make_float2(acc[mt][nt][2] + bx, acc[mt][nt][3] + by);
        }

    pdl_trigger();   // gh stores issued; dependent gate_ln may launch
}

// ---------------------------------------------------------------------------
// Per-step gates + hidden update + LayerNorm (R7/R10-proven).
// Also writes the split-bf16 h for the next step's GEMM.
// ---------------------------------------------------------------------------
__global__ __launch_bounds__(256) void gate_ln(
    int t, const float* __restrict__ masks,
    const float* __restrict__ ln_w, const float* __restrict__ ln_b,
    float* __restrict__ y)
{
    __shared__ float red1[8];
    __shared__ float red2[8];
    __shared__ float stat[2];

    const int b   = blockIdx.x;
    const int tid = threadIdx.x;
    const int j   = tid * 2;

    const float m = masks[t * BB + b];        // constant input: pre-wait OK
    pdl_wait();                               // gh(t) from predecessor GEMM

    const float* gi = g_gi + ((size_t)t * BB + b) * G3;
    const float* gh = g_gh + (size_t)b * G3;
    float* hp = g_h + (size_t)b * HH;

    float2 hv  = *(float2*)(hp + j);
    float2 gir = *(const float2*)(gi + j);
    float2 giz = *(const float2*)(gi + HH + j);
    float2 gin = *(const float2*)(gi + 2 * HH + j);
    float2 ghr = *(const float2*)(gh + j);
    float2 ghz = *(const float2*)(gh + HH + j);
    float2 ghn = *(const float2*)(gh + 2 * HH + j);

    const float r0 = 1.f / (1.f + expf(-(gir.x + ghr.x)));
    const float r1 = 1.f / (1.f + expf(-(gir.y + ghr.y)));
    const float z0 = 1.f / (1.f + expf(-(giz.x + ghz.x)));
    const float z1 = 1.f / (1.f + expf(-(giz.y + ghz.y)));
    const float n0 = tanhf(gin.x + r0 * ghn.x);
    const float n1 = tanhf(gin.y + r1 * ghn.y);
    const float h0 = (1.f - z0) * n0 + z0 * (hv.x * m);
    const float h1 = (1.f - z1) * n1 + z1 * (hv.y * m);

    *(float2*)(hp + j) = make_float2(h0, h1);
    ((uint2*)g_hs)[(size_t)b * (HH / 2) + tid] = split2(h0, h1);

    float s1 = h0 + h1, s2 = h0 * h0 + h1 * h1;
    #pragma unroll
    for (int o = 16; o > 0; o >>= 1) {
        s1 += __shfl_xor_sync(0xFFFFFFFFu, s1, o);
        s2 += __shfl_xor_sync(0xFFFFFFFFu, s2, o);
    }
    const int warp = tid >> 5, lane = tid & 31;
    if (lane == 0) { red1[warp] = s1; red2[warp] = s2; }
    __syncthreads();
    if (warp == 0) {
        s1 = (lane < 8) ? red1[lane] : 0.0f;
        s2 = (lane < 8) ? red2[lane] : 0.0f;
        #pragma unroll
        for (int o = 4; o > 0; o >>= 1) {
            s1 += __shfl_xor_sync(0xFFFFFFFFu, s1, o);
            s2 += __shfl_xor_sync(0xFFFFFFFFu, s2, o);
        }
        if (lane == 0) {
            const float mu = s1 * (1.0f / HH);
            stat[0] = mu;
            stat[1] = rsqrtf(s2 * (1.0f / HH) - mu * mu + LN_EPS);
        }
    }
    __syncthreads();

    const float mu = stat[0], rstd = stat[1];
    float2 w = *(const float2*)(ln_w + j);
    float2 bta = *(const float2*)(ln_b + j);
    float2 o;
    o.x = (h0 - mu) * rstd * w.x + bta.x;
    o.y = (h1 - mu) * rstd * w.y + bta.y;
    *(float2*)(y + ((size_t)t * BB + b) * HH + j) = o;

    pdl_trigger();   // h/hs stores issued; next step's GEMM may launch
}

// ---------------------------------------------------------------------------
// PDL launch helper
// ---------------------------------------------------------------------------
template<typename F, typename... Args>
static inline void launch_pdl(F f, dim3 grid, dim3 block, Args... args) {
    cudaLaunchConfig_t cfg = {};
    cfg.gridDim = grid;
    cfg.blockDim = block;
    cfg.dynamicSmemBytes = 0;
    cfg.stream = 0;
    cudaLaunchAttribute attr[1];
    attr[0].id = cudaLaunchAttributeProgrammaticStreamSerialization;
    attr[0].val.programmaticStreamSerializationAllowed = 1;
    cfg.attrs = attr;
    cfg.numAttrs = 1;
    cudaLaunchKernelEx(&cfg, f, args...);
}

// ---------------------------------------------------------------------------
extern "C" void kernel_launch(void* const* d_in, const int* in_sizes, int n_in,
                              void* d_out, int out_size)
{
    const float* x     = (const float*)d_in[0];
    const float* h0    = (const float*)d_in[1];
    const float* masks = (const float*)d_in[2];
    const float* W_ih  = (const float*)d_in[3];
    const float* W_hh  = (const float*)d_in[4];
    const float* b_ih  = (const float*)d_in[5];
    const float* b_hh  = (const float*)d_in[6];
    const float* ln_w  = (const float*)d_in[7];
    const float* ln_b  = (const float*)d_in[8];

    float* y  = (float*)d_out;
    float* hT = y + (size_t)TT * BB * HH;

    float *gi_p, *h_p;
    unsigned *xs_p, *wis_p, *whs_p, *hs_p;
    cudaGetSymbolAddress((void**)&gi_p,  g_gi);
    cudaGetSymbolAddress((void**)&h_p,   g_h);
    cudaGetSymbolAddress((void**)&xs_p,  g_xs);
    cudaGetSymbolAddress((void**)&wis_p, g_wis);
    cudaGetSymbolAddress((void**)&whs_p, g_whs);
    cudaGetSymbolAddress((void**)&hs_p,  g_hs);

    // Phase 0: one-time bf16 hi/lo splits
    const int npx = TT * BB * KK / 2;
    const int npw = G3 * KK / 2;
    const int nph = BB * HH / 2;
    split_pairs<<<(npx + 255) / 256, 256>>>(x,    xs_p,  npx);
    split_pairs<<<(npw + 255) / 256, 256>>>(W_ih, wis_p, npw);
    split_pairs<<<(npw + 255) / 256, 256>>>(W_hh, whs_p, npw);
    split_pairs<<<(nph + 255) / 256, 256>>>(h0,   hs_p,  nph);
    cudaMemcpyAsync(h_p, h0, (size_t)BB * HH * sizeof(float),
                    cudaMemcpyDeviceToDevice);

    // Phase 1: gi = x @ W_ih^T + b_ih (fully parallel)
    gemm_bf16s<<<dim3(G3 / 64, (TT * BB) / 64), 256>>>(xs_p, wis_p, b_ih, gi_p, G3);

    // Phase 2: sequential recurrence, PDL-chained two-kernel steps
    for (int t = 0; t < TT; t++) {
        launch_pdl(gemm_rec, dim3(G3 / 64, BB / 64), dim3(256),
                   masks + (size_t)t * BB, b_hh);
        launch_pdl(gate_ln, dim3(BB), dim3(256), t, masks, ln_w, ln_b, y);
    }

    // hT output
    cudaMemcpyAsync(hT, h_p, (size_t)BB * HH * sizeof(float),
                    cudaMemcpyDeviceToDevice);
}